// round 3
// baseline (speedup 1.0000x reference)
#include <cuda_runtime.h>
#include <math.h>

// ---------------- problem constants (fixed shapes) ----------------
#define TL      4        // layers
#define NB      8        // batch (sequences)
#define SQ      512      // new tokens per seq
#define DMODEL  1024
#define NH      16
#define DH      64
#define PAGE    16
#define PPS     80       // pages per seq
#define CACHED_TOK 768   // 48 pages * 16
#define KVLEN   1280
#define NTOK    4096     // NB * SQ
#define FFND    4096
#define NUM_PAGES 640

// ---------------- device scratch (no allocations allowed) ----------------
__device__ float g_x[NTOK * DMODEL];
__device__ float g_q[NTOK * DMODEL];
__device__ float g_k[NTOK * DMODEL];
__device__ float g_v[NTOK * DMODEL];
__device__ float g_attn[NTOK * DMODEL];
__device__ float g_tmp[NTOK * DMODEL];
__device__ float g_h[NTOK * FFND];

// ---------------- utility copy ----------------
__global__ void copy_f4(const float4* __restrict__ src, float4* __restrict__ dst, int n4) {
    int i = blockIdx.x * blockDim.x + threadIdx.x;
    if (i < n4) dst[i] = src[i];
}

// ---------------- SGEMM: C[M,N] = A[M,K] @ W[K,N] + bias (opt. GELU) ----------------
// BM=BN=128, BK=8, 256 threads, 8x8 per thread, double-buffered smem.
// All dims are multiples of 128 in this problem -> no bounds checks.
template<int GELU>
__launch_bounds__(256, 2)
__global__ void sgemm_bias(const float* __restrict__ A, const float* __restrict__ W,
                           const float* __restrict__ bias, float* __restrict__ C,
                           int M, int N, int K) {
    __shared__ float As[2][8][128];
    __shared__ float Bs[2][8][128];

    const int tid = threadIdx.x;
    const int tx = tid & 15;         // 0..15 -> N sub
    const int ty = tid >> 4;         // 0..15 -> M sub
    const int row0 = blockIdx.y * 128;
    const int col0 = blockIdx.x * 128;

    // A tile load mapping: 128 rows x 8 k -> 256 float4 (one per thread)
    const int aRow = tid >> 1;            // 0..127
    const int aK   = (tid & 1) * 4;       // 0 or 4
    // B tile load mapping: 8 rows x 128 cols -> 256 float4
    const int bRow = tid >> 5;            // 0..7
    const int bCol = (tid & 31) * 4;      // 0..124

    const float* Aptr = A + (size_t)(row0 + aRow) * K + aK;
    const float* Bptr = W + (size_t)bRow * N + col0 + bCol;

    float acc[8][8];
    #pragma unroll
    for (int i = 0; i < 8; ++i)
        #pragma unroll
        for (int j = 0; j < 8; ++j) acc[i][j] = 0.f;

    // prologue: tile 0
    {
        float4 av = *(const float4*)Aptr;
        As[0][aK + 0][aRow] = av.x; As[0][aK + 1][aRow] = av.y;
        As[0][aK + 2][aRow] = av.z; As[0][aK + 3][aRow] = av.w;
        float4 bv = *(const float4*)Bptr;
        *(float4*)&Bs[0][bRow][bCol] = bv;
    }
    __syncthreads();

    const int nt = K >> 3;
    int buf = 0;
    for (int t = 0; t < nt; ++t) {
        float4 an, bn;
        const bool more = (t + 1 < nt);
        if (more) {
            an = *(const float4*)(Aptr + (size_t)(t + 1) * 8);
            bn = *(const float4*)(Bptr + (size_t)(t + 1) * 8 * N);
        }
        #pragma unroll
        for (int k = 0; k < 8; ++k) {
            float a[8], b[8];
            *(float4*)&a[0] = *(const float4*)&As[buf][k][ty * 8];
            *(float4*)&a[4] = *(const float4*)&As[buf][k][ty * 8 + 4];
            *(float4*)&b[0] = *(const float4*)&Bs[buf][k][tx * 8];
            *(float4*)&b[4] = *(const float4*)&Bs[buf][k][tx * 8 + 4];
            #pragma unroll
            for (int i = 0; i < 8; ++i)
                #pragma unroll
                for (int j = 0; j < 8; ++j)
                    acc[i][j] = fmaf(a[i], b[j], acc[i][j]);
        }
        if (more) {
            buf ^= 1;
            As[buf][aK + 0][aRow] = an.x; As[buf][aK + 1][aRow] = an.y;
            As[buf][aK + 2][aRow] = an.z; As[buf][aK + 3][aRow] = an.w;
            *(float4*)&Bs[buf][bRow][bCol] = bn;
            __syncthreads();
        }
    }

    // epilogue: bias (+ exact GELU), vectorized stores
    float bf[8];
    *(float4*)&bf[0] = *(const float4*)(bias + col0 + tx * 8);
    *(float4*)&bf[4] = *(const float4*)(bias + col0 + tx * 8 + 4);
    #pragma unroll
    for (int i = 0; i < 8; ++i) {
        float v[8];
        #pragma unroll
        for (int j = 0; j < 8; ++j) {
            float s = acc[i][j] + bf[j];
            if (GELU) s = s * normcdff(s);   // exact gelu: x * Phi(x)
            v[j] = s;
        }
        float* cp = C + (size_t)(row0 + ty * 8 + i) * N + col0 + tx * 8;
        *(float4*)cp       = *(float4*)&v[0];
        *(float4*)(cp + 4) = *(float4*)&v[4];
    }
}

// ---------------- fused paged-KV flash attention ----------------
// grid: (SQ/64, NH, NB), 256 threads. q-tile 64 rows, kv tiles of 64.
// smem (dynamic): Qt[64d][68], Kt[64d][68], Vs[64j][68], Ps[64i][68], stats.
#define ATTN_SMEM_FLOATS (4 * 64 * 68 + 3 * 64)
#define ATTN_SMEM_BYTES  (ATTN_SMEM_FLOATS * 4)

__launch_bounds__(256)
__global__ void attn_kernel(const float* __restrict__ q, const float* __restrict__ knew,
                            const float* __restrict__ vnew, const float* __restrict__ ptab,
                            const int* __restrict__ kvidx, float* __restrict__ out) {
    const int qt = blockIdx.x, h = blockIdx.y, b = blockIdx.z;
    extern __shared__ float sm[];
    float* Qt   = sm;                    // [d][i] stride 68
    float* Kt   = Qt + 64 * 68;          // [d][j] stride 68
    float* Vsm  = Kt + 64 * 68;          // [j][d] stride 68
    float* Ps   = Vsm + 64 * 68;         // [i][j] stride 68
    float* rowM = Ps + 64 * 68;
    float* rowL = rowM + 64;
    float* rowC = rowL + 64;

    const int tid = threadIdx.x;
    const int tx = tid & 15, ty = tid >> 4;
    const float scale = 0.125f;  // DH^-0.5

    // load Q tile transposed (scaled)
    #pragma unroll
    for (int r = 0; r < 4; ++r) {
        int idx = tid + r * 256;            // 0..1023 float4 units
        int tok = idx >> 4;
        int d4  = (idx & 15) << 2;
        float4 v = *(const float4*)(q + (size_t)(b * SQ + qt * 64 + tok) * DMODEL + h * DH + d4);
        Qt[(d4 + 0) * 68 + tok] = v.x * scale;
        Qt[(d4 + 1) * 68 + tok] = v.y * scale;
        Qt[(d4 + 2) * 68 + tok] = v.z * scale;
        Qt[(d4 + 3) * 68 + tok] = v.w * scale;
    }
    if (tid < 64) { rowM[tid] = -1e30f; rowL[tid] = 0.f; }
    float O[4][4] = {{0.f}};
    __syncthreads();

    for (int kt = 0; kt < KVLEN / 64; ++kt) {
        // load K (transposed) and V tiles, paged or fresh
        #pragma unroll
        for (int r = 0; r < 4; ++r) {
            int idx = tid + r * 256;
            int tok = idx >> 4;
            int d4  = (idx & 15) << 2;
            int kv = kt * 64 + tok;
            const float *kp, *vp;
            if (kv < CACHED_TOK) {
                int page = kvidx[b * PPS + (kv >> 4)];
                size_t base = (size_t)page * (2 * PAGE * NH * DH)
                            + (size_t)(kv & 15) * (NH * DH) + h * DH + d4;
                kp = ptab + base;
                vp = ptab + base + PAGE * NH * DH;
            } else {
                size_t off = (size_t)(b * SQ + (kv - CACHED_TOK)) * DMODEL + h * DH + d4;
                kp = knew + off;
                vp = vnew + off;
            }
            float4 kk = *(const float4*)kp;
            Kt[(d4 + 0) * 68 + tok] = kk.x;
            Kt[(d4 + 1) * 68 + tok] = kk.y;
            Kt[(d4 + 2) * 68 + tok] = kk.z;
            Kt[(d4 + 3) * 68 + tok] = kk.w;
            *(float4*)&Vsm[tok * 68 + d4] = *(const float4*)vp;
        }
        __syncthreads();

        // S = (Q*scale) @ K^T  -> each thread 4x4
        float s[4][4] = {{0.f}};
        #pragma unroll
        for (int d = 0; d < DH; ++d) {
            float aq[4], bk[4];
            *(float4*)aq = *(const float4*)&Qt[d * 68 + ty * 4];
            *(float4*)bk = *(const float4*)&Kt[d * 68 + tx * 4];
            #pragma unroll
            for (int i = 0; i < 4; ++i)
                #pragma unroll
                for (int j = 0; j < 4; ++j)
                    s[i][j] = fmaf(aq[i], bk[j], s[i][j]);
        }
        #pragma unroll
        for (int i = 0; i < 4; ++i)
            #pragma unroll
            for (int j = 0; j < 4; ++j)
                Ps[(ty * 4 + i) * 68 + tx * 4 + j] = s[i][j];
        __syncthreads();

        // online softmax: 4 threads per row
        {
            int row = tid >> 2, quad = tid & 3;
            float m = -1e30f;
            #pragma unroll
            for (int j = 0; j < 16; ++j) m = fmaxf(m, Ps[row * 68 + quad * 16 + j]);
            m = fmaxf(m, __shfl_xor_sync(0xffffffffu, m, 1));
            m = fmaxf(m, __shfl_xor_sync(0xffffffffu, m, 2));
            float mnew = fmaxf(rowM[row], m);
            float ssum = 0.f;
            #pragma unroll
            for (int j = 0; j < 16; ++j) {
                float p = __expf(Ps[row * 68 + quad * 16 + j] - mnew);
                Ps[row * 68 + quad * 16 + j] = p;
                ssum += p;
            }
            ssum += __shfl_xor_sync(0xffffffffu, ssum, 1);
            ssum += __shfl_xor_sync(0xffffffffu, ssum, 2);
            if (quad == 0) {
                float corr = __expf(rowM[row] - mnew);
                rowC[row] = corr;
                rowL[row] = rowL[row] * corr + ssum;
                rowM[row] = mnew;
            }
        }
        __syncthreads();

        // rescale O, accumulate P @ V
        float c[4];
        #pragma unroll
        for (int i = 0; i < 4; ++i) c[i] = rowC[ty * 4 + i];
        #pragma unroll
        for (int i = 0; i < 4; ++i)
            #pragma unroll
            for (int j = 0; j < 4; ++j) O[i][j] *= c[i];

        #pragma unroll
        for (int j = 0; j < 64; ++j) {
            float vv[4];
            *(float4*)vv = *(const float4*)&Vsm[j * 68 + tx * 4];
            float p0 = Ps[(ty * 4 + 0) * 68 + j];
            float p1 = Ps[(ty * 4 + 1) * 68 + j];
            float p2 = Ps[(ty * 4 + 2) * 68 + j];
            float p3 = Ps[(ty * 4 + 3) * 68 + j];
            #pragma unroll
            for (int jj = 0; jj < 4; ++jj) {
                O[0][jj] = fmaf(p0, vv[jj], O[0][jj]);
                O[1][jj] = fmaf(p1, vv[jj], O[1][jj]);
                O[2][jj] = fmaf(p2, vv[jj], O[2][jj]);
                O[3][jj] = fmaf(p3, vv[jj], O[3][jj]);
            }
        }
        __syncthreads();
    }

    // normalize and write out (b, q, h, dh) flattened -> [T, D]
    #pragma unroll
    for (int i = 0; i < 4; ++i) {
        float inv = 1.0f / rowL[ty * 4 + i];
        float4 o;
        o.x = O[i][0] * inv; o.y = O[i][1] * inv;
        o.z = O[i][2] * inv; o.w = O[i][3] * inv;
        *(float4*)(out + (size_t)(b * SQ + qt * 64 + ty * 4 + i) * DMODEL + h * DH + tx * 4) = o;
    }
}

// ---------------- fused residual-add + LayerNorm (one block per row) ----------------
__launch_bounds__(256)
__global__ void ln_kernel(const float* __restrict__ resid, const float* __restrict__ y,
                          const float* __restrict__ gg, const float* __restrict__ bb,
                          float* __restrict__ out) {
    const int row = blockIdx.x, tid = threadIdx.x;
    __shared__ float redS[8], redS2[8];
    float4 rv = *(const float4*)(resid + (size_t)row * DMODEL + tid * 4);
    float4 yv = *(const float4*)(y     + (size_t)row * DMODEL + tid * 4);
    float v0 = rv.x + yv.x, v1 = rv.y + yv.y, v2 = rv.z + yv.z, v3 = rv.w + yv.w;
    float s  = v0 + v1 + v2 + v3;
    float s2 = v0 * v0 + v1 * v1 + v2 * v2 + v3 * v3;
    #pragma unroll
    for (int o = 16; o > 0; o >>= 1) {
        s  += __shfl_xor_sync(0xffffffffu, s,  o);
        s2 += __shfl_xor_sync(0xffffffffu, s2, o);
    }
    if ((tid & 31) == 0) { redS[tid >> 5] = s; redS2[tid >> 5] = s2; }
    __syncthreads();
    if (tid < 32) {
        float a  = (tid < 8) ? redS[tid]  : 0.f;
        float a2 = (tid < 8) ? redS2[tid] : 0.f;
        #pragma unroll
        for (int o = 4; o > 0; o >>= 1) {
            a  += __shfl_xor_sync(0xffffffffu, a,  o);
            a2 += __shfl_xor_sync(0xffffffffu, a2, o);
        }
        if (tid == 0) { redS[0] = a; redS2[0] = a2; }
    }
    __syncthreads();
    const float mean = redS[0] * (1.f / DMODEL);
    const float var  = redS2[0] * (1.f / DMODEL) - mean * mean;
    const float inv  = rsqrtf(var + 1e-5f);
    float4 gv = *(const float4*)(gg + tid * 4);
    float4 bv = *(const float4*)(bb + tid * 4);
    float4 o;
    o.x = (v0 - mean) * inv * gv.x + bv.x;
    o.y = (v1 - mean) * inv * gv.y + bv.y;
    o.z = (v2 - mean) * inv * gv.z + bv.z;
    o.w = (v3 - mean) * inv * gv.w + bv.w;
    *(float4*)(out + (size_t)row * DMODEL + tid * 4) = o;
}

// ---------------- launcher ----------------
extern "C" void kernel_launch(void* const* d_in, const int* in_sizes, int n_in,
                              void* d_out, int out_size) {
    const float* x      = (const float*)d_in[0];
    const int*   kvidx  = (const int*)d_in[3];
    const float* ptab   = (const float*)d_in[5];
    const float* Wq = (const float*)d_in[6];
    const float* bq = (const float*)d_in[7];
    const float* Wk = (const float*)d_in[8];
    const float* bk = (const float*)d_in[9];
    const float* Wv = (const float*)d_in[10];
    const float* bv = (const float*)d_in[11];
    const float* Wo = (const float*)d_in[12];
    const float* bo = (const float*)d_in[13];
    const float* ln1g = (const float*)d_in[14];
    const float* ln1b = (const float*)d_in[15];
    const float* W1 = (const float*)d_in[16];
    const float* b1 = (const float*)d_in[17];
    const float* W2 = (const float*)d_in[18];
    const float* b2 = (const float*)d_in[19];
    const float* ln2g = (const float*)d_in[20];
    const float* ln2b = (const float*)d_in[21];

    float *gx, *gq, *gk, *gv, *ga, *gt, *gh;
    cudaGetSymbolAddress((void**)&gx, g_x);
    cudaGetSymbolAddress((void**)&gq, g_q);
    cudaGetSymbolAddress((void**)&gk, g_k);
    cudaGetSymbolAddress((void**)&gv, g_v);
    cudaGetSymbolAddress((void**)&ga, g_attn);
    cudaGetSymbolAddress((void**)&gt, g_tmp);
    cudaGetSymbolAddress((void**)&gh, g_h);

    cudaFuncSetAttribute((const void*)attn_kernel,
                         cudaFuncAttributeMaxDynamicSharedMemorySize, ATTN_SMEM_BYTES);

    const int n4 = NTOK * DMODEL / 4;
    copy_f4<<<(n4 + 255) / 256, 256>>>((const float4*)x, (float4*)gx, n4);

    dim3 gProj(DMODEL / 128, NTOK / 128);  // (8, 32)
    dim3 gF1(FFND / 128, NTOK / 128);      // (32, 32)
    dim3 gAttn(SQ / 64, NH, NB);           // (8, 16, 8)

    for (int l = 0; l < TL; ++l) {
        const float* Wq_l = Wq + (size_t)l * DMODEL * DMODEL;
        const float* Wk_l = Wk + (size_t)l * DMODEL * DMODEL;
        const float* Wv_l = Wv + (size_t)l * DMODEL * DMODEL;
        const float* Wo_l = Wo + (size_t)l * DMODEL * DMODEL;
        const float* W1_l = W1 + (size_t)l * DMODEL * FFND;
        const float* W2_l = W2 + (size_t)l * FFND * DMODEL;
        const float* ptab_l = ptab + (size_t)l * NUM_PAGES * 2 * PAGE * NH * DH;

        sgemm_bias<0><<<gProj, 256>>>(gx, Wq_l, bq + l * DMODEL, gq, NTOK, DMODEL, DMODEL);
        sgemm_bias<0><<<gProj, 256>>>(gx, Wk_l, bk + l * DMODEL, gk, NTOK, DMODEL, DMODEL);
        sgemm_bias<0><<<gProj, 256>>>(gx, Wv_l, bv + l * DMODEL, gv, NTOK, DMODEL, DMODEL);

        attn_kernel<<<gAttn, 256, ATTN_SMEM_BYTES>>>(gq, gk, gv, ptab_l, kvidx, ga);

        sgemm_bias<0><<<gProj, 256>>>(ga, Wo_l, bo + l * DMODEL, gt, NTOK, DMODEL, DMODEL);
        ln_kernel<<<NTOK, 256>>>(gx, gt, ln1g + l * DMODEL, ln1b + l * DMODEL, gx);

        sgemm_bias<1><<<gF1, 256>>>(gx, W1_l, b1 + l * FFND, gh, NTOK, FFND, DMODEL);
        sgemm_bias<0><<<gProj, 256>>>(gh, W2_l, b2 + l * DMODEL, gt, NTOK, DMODEL, FFND);
        ln_kernel<<<NTOK, 256>>>(gx, gt, ln2g + l * DMODEL, ln2b + l * DMODEL, gx);
    }

    copy_f4<<<(n4 + 255) / 256, 256>>>((const float4*)gx, (float4*)d_out, n4);
}

// round 4
// speedup vs baseline: 1.9340x; 1.9340x over previous
#include <cuda_runtime.h>
#include <math.h>
#include <stdint.h>

// ---------------- problem constants (fixed shapes) ----------------
#define TL      4        // layers
#define NB      8        // batch (sequences)
#define SQ      512      // new tokens per seq
#define DMODEL  1024
#define NH      16
#define DH      64
#define PAGE    16
#define PPS     80       // pages per seq
#define CACHED_TOK 768   // 48 pages * 16
#define KVLEN   1280
#define NTOK    4096     // NB * SQ
#define FFND    4096
#define NUM_PAGES 640

// ---------------- device scratch (no allocations allowed) ----------------
__device__ float g_x[NTOK * DMODEL];
__device__ float g_q[NTOK * DMODEL];
__device__ float g_k[NTOK * DMODEL];
__device__ float g_v[NTOK * DMODEL];
__device__ float g_attn[NTOK * DMODEL];
__device__ float g_tmp[NTOK * DMODEL];
__device__ float g_h[NTOK * FFND];

// ---------------- utility copy ----------------
__global__ void copy_f4(const float4* __restrict__ src, float4* __restrict__ dst, int n4) {
    int i = blockIdx.x * blockDim.x + threadIdx.x;
    if (i < n4) dst[i] = src[i];
}

// ---------------- TF32 helpers ----------------
__device__ __forceinline__ uint32_t f2tf(float x) {
    uint32_t r;
    asm("cvt.rna.tf32.f32 %0, %1;" : "=r"(r) : "f"(x));
    return r;
}

__device__ __forceinline__ void mma_tf32(float d[4],
                                         uint32_t a0, uint32_t a1, uint32_t a2, uint32_t a3,
                                         uint32_t b0, uint32_t b1) {
    asm volatile(
        "mma.sync.aligned.m16n8k8.row.col.f32.tf32.tf32.f32 "
        "{%0,%1,%2,%3}, {%4,%5,%6,%7}, {%8,%9}, {%0,%1,%2,%3};\n"
        : "+f"(d[0]), "+f"(d[1]), "+f"(d[2]), "+f"(d[3])
        : "r"(a0), "r"(a1), "r"(a2), "r"(a3), "r"(b0), "r"(b1));
}

// ---------------- TF32 tensor-core GEMM ----------------
// C[M,N] = A[M,K] @ W[K,N] + bias (opt. exact GELU)
// Block tile 128x128, BK=16, 256 threads = 8 warps, warp tile 64x32,
// per warp 4x4 atoms of m16n8k8. Double-buffered smem, register-staged
// global prefetch with tf32 conversion at staging time.
// Smem bank analysis: As[row][k] stride 20 -> fragment load banks (4m+k)%32
// all distinct; Bs[k][n] stride 136 (=8 mod 32) -> banks (8k+n)%32 all distinct.
template<int GELU>
__launch_bounds__(256, 2)
__global__ void sgemm_tc(const float* __restrict__ A, const float* __restrict__ W,
                         const float* __restrict__ bias, float* __restrict__ C,
                         int M, int N, int K) {
    __shared__ uint32_t As[2][128][20];
    __shared__ uint32_t Bs[2][16][136];

    const int tid  = threadIdx.x;
    const int lane = tid & 31;
    const int wid  = tid >> 5;
    const int wm   = wid & 1;           // 0..1 (M dir, 64 rows each)
    const int wn   = wid >> 1;          // 0..3 (N dir, 32 cols each)
    const int g    = lane >> 2;         // 0..7
    const int tg   = lane & 3;          // 0..3

    const int row0 = blockIdx.y * 128;
    const int col0 = blockIdx.x * 128;

    // Global load mapping (2 float4 per thread per tile for each of A, B)
    // A: idx = tid + i*256 -> row = idx>>2 (0..127), kq = idx&3 (0..3)
    // B: idx = tid + i*256 -> kr  = idx>>5 (0..15),  nq = idx&31 (0..31)
    const int aRow0 = (tid + 0)   >> 2, aKq0 = (tid + 0)   & 3;
    const int aRow1 = (tid + 256) >> 2, aKq1 = (tid + 256) & 3;
    const int bKr0  = (tid + 0)   >> 5, bNq0 = (tid + 0)   & 31;
    const int bKr1  = (tid + 256) >> 5, bNq1 = (tid + 256) & 31;

    const float* Ap0 = A + (size_t)(row0 + aRow0) * K + aKq0 * 4;
    const float* Ap1 = A + (size_t)(row0 + aRow1) * K + aKq1 * 4;
    const float* Bp0 = W + (size_t)bKr0 * N + col0 + bNq0 * 4;
    const float* Bp1 = W + (size_t)bKr1 * N + col0 + bNq1 * 4;

    float acc[4][4][4];
    #pragma unroll
    for (int i = 0; i < 4; ++i)
        #pragma unroll
        for (int j = 0; j < 4; ++j)
            #pragma unroll
            for (int e = 0; e < 4; ++e) acc[i][j][e] = 0.f;

    // ---- prologue: tile 0 ----
    {
        float4 a0 = *(const float4*)Ap0;
        float4 a1 = *(const float4*)Ap1;
        float4 b0 = *(const float4*)Bp0;
        float4 b1 = *(const float4*)Bp1;
        uint4 t;
        t.x = f2tf(a0.x); t.y = f2tf(a0.y); t.z = f2tf(a0.z); t.w = f2tf(a0.w);
        *(uint4*)&As[0][aRow0][aKq0 * 4] = t;
        t.x = f2tf(a1.x); t.y = f2tf(a1.y); t.z = f2tf(a1.z); t.w = f2tf(a1.w);
        *(uint4*)&As[0][aRow1][aKq1 * 4] = t;
        t.x = f2tf(b0.x); t.y = f2tf(b0.y); t.z = f2tf(b0.z); t.w = f2tf(b0.w);
        *(uint4*)&Bs[0][bKr0][bNq0 * 4] = t;
        t.x = f2tf(b1.x); t.y = f2tf(b1.y); t.z = f2tf(b1.z); t.w = f2tf(b1.w);
        *(uint4*)&Bs[0][bKr1][bNq1 * 4] = t;
    }
    __syncthreads();

    const int nt = K >> 4;
    int buf = 0;
    for (int t = 0; t < nt; ++t) {
        float4 na0, na1, nb0, nb1;
        const bool more = (t + 1 < nt);
        if (more) {
            na0 = *(const float4*)(Ap0 + (size_t)(t + 1) * 16);
            na1 = *(const float4*)(Ap1 + (size_t)(t + 1) * 16);
            nb0 = *(const float4*)(Bp0 + (size_t)(t + 1) * 16 * N);
            nb1 = *(const float4*)(Bp1 + (size_t)(t + 1) * 16 * N);
        }

        // ---- compute: two k8 steps from smem[buf] ----
        #pragma unroll
        for (int ks = 0; ks < 2; ++ks) {
            const int k0 = ks * 8;
            uint32_t af[4][4], bf[4][2];
            #pragma unroll
            for (int mt = 0; mt < 4; ++mt) {
                const int r = wm * 64 + mt * 16 + g;
                af[mt][0] = As[buf][r][k0 + tg];
                af[mt][1] = As[buf][r + 8][k0 + tg];
                af[mt][2] = As[buf][r][k0 + tg + 4];
                af[mt][3] = As[buf][r + 8][k0 + tg + 4];
            }
            #pragma unroll
            for (int ntc = 0; ntc < 4; ++ntc) {
                const int c = wn * 32 + ntc * 8 + g;
                bf[ntc][0] = Bs[buf][k0 + tg][c];
                bf[ntc][1] = Bs[buf][k0 + tg + 4][c];
            }
            #pragma unroll
            for (int mt = 0; mt < 4; ++mt)
                #pragma unroll
                for (int ntc = 0; ntc < 4; ++ntc)
                    mma_tf32(acc[mt][ntc], af[mt][0], af[mt][1], af[mt][2], af[mt][3],
                             bf[ntc][0], bf[ntc][1]);
        }

        if (more) {
            buf ^= 1;
            uint4 s;
            s.x = f2tf(na0.x); s.y = f2tf(na0.y); s.z = f2tf(na0.z); s.w = f2tf(na0.w);
            *(uint4*)&As[buf][aRow0][aKq0 * 4] = s;
            s.x = f2tf(na1.x); s.y = f2tf(na1.y); s.z = f2tf(na1.z); s.w = f2tf(na1.w);
            *(uint4*)&As[buf][aRow1][aKq1 * 4] = s;
            s.x = f2tf(nb0.x); s.y = f2tf(nb0.y); s.z = f2tf(nb0.z); s.w = f2tf(nb0.w);
            *(uint4*)&Bs[buf][bKr0][bNq0 * 4] = s;
            s.x = f2tf(nb1.x); s.y = f2tf(nb1.y); s.z = f2tf(nb1.z); s.w = f2tf(nb1.w);
            *(uint4*)&Bs[buf][bKr1][bNq1 * 4] = s;
            __syncthreads();
        }
    }

    // ---- epilogue: bias (+ exact GELU), float2 stores ----
    #pragma unroll
    for (int ntc = 0; ntc < 4; ++ntc) {
        const int col = col0 + wn * 32 + ntc * 8 + 2 * tg;
        const float2 bb = *(const float2*)(bias + col);
        #pragma unroll
        for (int mt = 0; mt < 4; ++mt) {
            const int row = row0 + wm * 64 + mt * 16 + g;
            float2 lo, hi;
            lo.x = acc[mt][ntc][0] + bb.x;
            lo.y = acc[mt][ntc][1] + bb.y;
            hi.x = acc[mt][ntc][2] + bb.x;
            hi.y = acc[mt][ntc][3] + bb.y;
            if (GELU) {
                lo.x *= normcdff(lo.x); lo.y *= normcdff(lo.y);
                hi.x *= normcdff(hi.x); hi.y *= normcdff(hi.y);
            }
            *(float2*)(C + (size_t)row * N + col)       = lo;
            *(float2*)(C + (size_t)(row + 8) * N + col) = hi;
        }
    }
}

// ---------------- fused paged-KV flash attention ----------------
// grid: (SQ/64, NH, NB), 256 threads. q-tile 64 rows, kv tiles of 64.
#define ATTN_SMEM_FLOATS (4 * 64 * 68 + 3 * 64)
#define ATTN_SMEM_BYTES  (ATTN_SMEM_FLOATS * 4)

__launch_bounds__(256)
__global__ void attn_kernel(const float* __restrict__ q, const float* __restrict__ knew,
                            const float* __restrict__ vnew, const float* __restrict__ ptab,
                            const int* __restrict__ kvidx, float* __restrict__ out) {
    const int qt = blockIdx.x, h = blockIdx.y, b = blockIdx.z;
    extern __shared__ float sm[];
    float* Qt   = sm;                    // [d][i] stride 68
    float* Kt   = Qt + 64 * 68;          // [d][j] stride 68
    float* Vsm  = Kt + 64 * 68;          // [j][d] stride 68
    float* Ps   = Vsm + 64 * 68;         // [i][j] stride 68
    float* rowM = Ps + 64 * 68;
    float* rowL = rowM + 64;
    float* rowC = rowL + 64;

    const int tid = threadIdx.x;
    const int tx = tid & 15, ty = tid >> 4;
    const float scale = 0.125f;  // DH^-0.5

    #pragma unroll
    for (int r = 0; r < 4; ++r) {
        int idx = tid + r * 256;
        int tok = idx >> 4;
        int d4  = (idx & 15) << 2;
        float4 v = *(const float4*)(q + (size_t)(b * SQ + qt * 64 + tok) * DMODEL + h * DH + d4);
        Qt[(d4 + 0) * 68 + tok] = v.x * scale;
        Qt[(d4 + 1) * 68 + tok] = v.y * scale;
        Qt[(d4 + 2) * 68 + tok] = v.z * scale;
        Qt[(d4 + 3) * 68 + tok] = v.w * scale;
    }
    if (tid < 64) { rowM[tid] = -1e30f; rowL[tid] = 0.f; }
    float O[4][4] = {{0.f}};
    __syncthreads();

    for (int kt = 0; kt < KVLEN / 64; ++kt) {
        #pragma unroll
        for (int r = 0; r < 4; ++r) {
            int idx = tid + r * 256;
            int tok = idx >> 4;
            int d4  = (idx & 15) << 2;
            int kv = kt * 64 + tok;
            const float *kp, *vp;
            if (kv < CACHED_TOK) {
                int page = kvidx[b * PPS + (kv >> 4)];
                size_t base = (size_t)page * (2 * PAGE * NH * DH)
                            + (size_t)(kv & 15) * (NH * DH) + h * DH + d4;
                kp = ptab + base;
                vp = ptab + base + PAGE * NH * DH;
            } else {
                size_t off = (size_t)(b * SQ + (kv - CACHED_TOK)) * DMODEL + h * DH + d4;
                kp = knew + off;
                vp = vnew + off;
            }
            float4 kk = *(const float4*)kp;
            Kt[(d4 + 0) * 68 + tok] = kk.x;
            Kt[(d4 + 1) * 68 + tok] = kk.y;
            Kt[(d4 + 2) * 68 + tok] = kk.z;
            Kt[(d4 + 3) * 68 + tok] = kk.w;
            *(float4*)&Vsm[tok * 68 + d4] = *(const float4*)vp;
        }
        __syncthreads();

        float s[4][4] = {{0.f}};
        #pragma unroll
        for (int d = 0; d < DH; ++d) {
            float aq[4], bk[4];
            *(float4*)aq = *(const float4*)&Qt[d * 68 + ty * 4];
            *(float4*)bk = *(const float4*)&Kt[d * 68 + tx * 4];
            #pragma unroll
            for (int i = 0; i < 4; ++i)
                #pragma unroll
                for (int j = 0; j < 4; ++j)
                    s[i][j] = fmaf(aq[i], bk[j], s[i][j]);
        }
        #pragma unroll
        for (int i = 0; i < 4; ++i)
            #pragma unroll
            for (int j = 0; j < 4; ++j)
                Ps[(ty * 4 + i) * 68 + tx * 4 + j] = s[i][j];
        __syncthreads();

        {
            int row = tid >> 2, quad = tid & 3;
            float m = -1e30f;
            #pragma unroll
            for (int j = 0; j < 16; ++j) m = fmaxf(m, Ps[row * 68 + quad * 16 + j]);
            m = fmaxf(m, __shfl_xor_sync(0xffffffffu, m, 1));
            m = fmaxf(m, __shfl_xor_sync(0xffffffffu, m, 2));
            float mnew = fmaxf(rowM[row], m);
            float ssum = 0.f;
            #pragma unroll
            for (int j = 0; j < 16; ++j) {
                float p = __expf(Ps[row * 68 + quad * 16 + j] - mnew);
                Ps[row * 68 + quad * 16 + j] = p;
                ssum += p;
            }
            ssum += __shfl_xor_sync(0xffffffffu, ssum, 1);
            ssum += __shfl_xor_sync(0xffffffffu, ssum, 2);
            if (quad == 0) {
                float corr = __expf(rowM[row] - mnew);
                rowC[row] = corr;
                rowL[row] = rowL[row] * corr + ssum;
                rowM[row] = mnew;
            }
        }
        __syncthreads();

        float c[4];
        #pragma unroll
        for (int i = 0; i < 4; ++i) c[i] = rowC[ty * 4 + i];
        #pragma unroll
        for (int i = 0; i < 4; ++i)
            #pragma unroll
            for (int j = 0; j < 4; ++j) O[i][j] *= c[i];

        #pragma unroll
        for (int j = 0; j < 64; ++j) {
            float vv[4];
            *(float4*)vv = *(const float4*)&Vsm[j * 68 + tx * 4];
            float p0 = Ps[(ty * 4 + 0) * 68 + j];
            float p1 = Ps[(ty * 4 + 1) * 68 + j];
            float p2 = Ps[(ty * 4 + 2) * 68 + j];
            float p3 = Ps[(ty * 4 + 3) * 68 + j];
            #pragma unroll
            for (int jj = 0; jj < 4; ++jj) {
                O[0][jj] = fmaf(p0, vv[jj], O[0][jj]);
                O[1][jj] = fmaf(p1, vv[jj], O[1][jj]);
                O[2][jj] = fmaf(p2, vv[jj], O[2][jj]);
                O[3][jj] = fmaf(p3, vv[jj], O[3][jj]);
            }
        }
        __syncthreads();
    }

    #pragma unroll
    for (int i = 0; i < 4; ++i) {
        float inv = 1.0f / rowL[ty * 4 + i];
        float4 o;
        o.x = O[i][0] * inv; o.y = O[i][1] * inv;
        o.z = O[i][2] * inv; o.w = O[i][3] * inv;
        *(float4*)(out + (size_t)(b * SQ + qt * 64 + ty * 4 + i) * DMODEL + h * DH + tx * 4) = o;
    }
}

// ---------------- fused residual-add + LayerNorm (one block per row) ----------------
__launch_bounds__(256)
__global__ void ln_kernel(const float* __restrict__ resid, const float* __restrict__ y,
                          const float* __restrict__ gg, const float* __restrict__ bb,
                          float* __restrict__ out) {
    const int row = blockIdx.x, tid = threadIdx.x;
    __shared__ float redS[8], redS2[8];
    float4 rv = *(const float4*)(resid + (size_t)row * DMODEL + tid * 4);
    float4 yv = *(const float4*)(y     + (size_t)row * DMODEL + tid * 4);
    float v0 = rv.x + yv.x, v1 = rv.y + yv.y, v2 = rv.z + yv.z, v3 = rv.w + yv.w;
    float s  = v0 + v1 + v2 + v3;
    float s2 = v0 * v0 + v1 * v1 + v2 * v2 + v3 * v3;
    #pragma unroll
    for (int o = 16; o > 0; o >>= 1) {
        s  += __shfl_xor_sync(0xffffffffu, s,  o);
        s2 += __shfl_xor_sync(0xffffffffu, s2, o);
    }
    if ((tid & 31) == 0) { redS[tid >> 5] = s; redS2[tid >> 5] = s2; }
    __syncthreads();
    if (tid < 32) {
        float a  = (tid < 8) ? redS[tid]  : 0.f;
        float a2 = (tid < 8) ? redS2[tid] : 0.f;
        #pragma unroll
        for (int o = 4; o > 0; o >>= 1) {
            a  += __shfl_xor_sync(0xffffffffu, a,  o);
            a2 += __shfl_xor_sync(0xffffffffu, a2, o);
        }
        if (tid == 0) { redS[0] = a; redS2[0] = a2; }
    }
    __syncthreads();
    const float mean = redS[0] * (1.f / DMODEL);
    const float var  = redS2[0] * (1.f / DMODEL) - mean * mean;
    const float inv  = rsqrtf(var + 1e-5f);
    float4 gv = *(const float4*)(gg + tid * 4);
    float4 bv = *(const float4*)(bb + tid * 4);
    float4 o;
    o.x = (v0 - mean) * inv * gv.x + bv.x;
    o.y = (v1 - mean) * inv * gv.y + bv.y;
    o.z = (v2 - mean) * inv * gv.z + bv.z;
    o.w = (v3 - mean) * inv * gv.w + bv.w;
    *(float4*)(out + (size_t)row * DMODEL + tid * 4) = o;
}

// ---------------- launcher ----------------
extern "C" void kernel_launch(void* const* d_in, const int* in_sizes, int n_in,
                              void* d_out, int out_size) {
    const float* x      = (const float*)d_in[0];
    const int*   kvidx  = (const int*)d_in[3];
    const float* ptab   = (const float*)d_in[5];
    const float* Wq = (const float*)d_in[6];
    const float* bq = (const float*)d_in[7];
    const float* Wk = (const float*)d_in[8];
    const float* bk = (const float*)d_in[9];
    const float* Wv = (const float*)d_in[10];
    const float* bv = (const float*)d_in[11];
    const float* Wo = (const float*)d_in[12];
    const float* bo = (const float*)d_in[13];
    const float* ln1g = (const float*)d_in[14];
    const float* ln1b = (const float*)d_in[15];
    const float* W1 = (const float*)d_in[16];
    const float* b1 = (const float*)d_in[17];
    const float* W2 = (const float*)d_in[18];
    const float* b2 = (const float*)d_in[19];
    const float* ln2g = (const float*)d_in[20];
    const float* ln2b = (const float*)d_in[21];

    float *gx, *gq, *gk, *gv, *ga, *gt, *gh;
    cudaGetSymbolAddress((void**)&gx, g_x);
    cudaGetSymbolAddress((void**)&gq, g_q);
    cudaGetSymbolAddress((void**)&gk, g_k);
    cudaGetSymbolAddress((void**)&gv, g_v);
    cudaGetSymbolAddress((void**)&ga, g_attn);
    cudaGetSymbolAddress((void**)&gt, g_tmp);
    cudaGetSymbolAddress((void**)&gh, g_h);

    cudaFuncSetAttribute((const void*)attn_kernel,
                         cudaFuncAttributeMaxDynamicSharedMemorySize, ATTN_SMEM_BYTES);

    const int n4 = NTOK * DMODEL / 4;
    copy_f4<<<(n4 + 255) / 256, 256>>>((const float4*)x, (float4*)gx, n4);

    dim3 gProj(DMODEL / 128, NTOK / 128);  // (8, 32)
    dim3 gF1(FFND / 128, NTOK / 128);      // (32, 32)
    dim3 gAttn(SQ / 64, NH, NB);           // (8, 16, 8)

    for (int l = 0; l < TL; ++l) {
        const float* Wq_l = Wq + (size_t)l * DMODEL * DMODEL;
        const float* Wk_l = Wk + (size_t)l * DMODEL * DMODEL;
        const float* Wv_l = Wv + (size_t)l * DMODEL * DMODEL;
        const float* Wo_l = Wo + (size_t)l * DMODEL * DMODEL;
        const float* W1_l = W1 + (size_t)l * DMODEL * FFND;
        const float* W2_l = W2 + (size_t)l * FFND * DMODEL;
        const float* ptab_l = ptab + (size_t)l * NUM_PAGES * 2 * PAGE * NH * DH;

        sgemm_tc<0><<<gProj, 256>>>(gx, Wq_l, bq + l * DMODEL, gq, NTOK, DMODEL, DMODEL);
        sgemm_tc<0><<<gProj, 256>>>(gx, Wk_l, bk + l * DMODEL, gk, NTOK, DMODEL, DMODEL);
        sgemm_tc<0><<<gProj, 256>>>(gx, Wv_l, bv + l * DMODEL, gv, NTOK, DMODEL, DMODEL);

        attn_kernel<<<gAttn, 256, ATTN_SMEM_BYTES>>>(gq, gk, gv, ptab_l, kvidx, ga);

        sgemm_tc<0><<<gProj, 256>>>(ga, Wo_l, bo + l * DMODEL, gt, NTOK, DMODEL, DMODEL);
        ln_kernel<<<NTOK, 256>>>(gx, gt, ln1g + l * DMODEL, ln1b + l * DMODEL, gx);

        sgemm_tc<1><<<gF1, 256>>>(gx, W1_l, b1 + l * FFND, gh, NTOK, FFND, DMODEL);
        sgemm_tc<0><<<gProj, 256>>>(gh, W2_l, b2 + l * DMODEL, gt, NTOK, DMODEL, FFND);
        ln_kernel<<<NTOK, 256>>>(gx, gt, ln2g + l * DMODEL, ln2b + l * DMODEL, gx);
    }

    copy_f4<<<(n4 + 255) / 256, 256>>>((const float4*)gx, (float4*)d_out, n4);
}

// round 7
// speedup vs baseline: 3.0909x; 1.5982x over previous
#include <cuda_runtime.h>
#include <math.h>
#include <stdint.h>

// ---------------- problem constants (fixed shapes) ----------------
#define TL      4
#define NB      8
#define SQ      512
#define DMODEL  1024
#define NH      16
#define DH      64
#define PAGE    16
#define PPS     80
#define CACHED_TOK 768
#define KVLEN   1280
#define NTOK    4096
#define FFND    4096
#define NUM_PAGES 640

// ---------------- device scratch ----------------
__device__ float    g_x[NTOK * DMODEL];
__device__ uint32_t g_xt[NTOK * DMODEL];        // tf32 copy of x
__device__ float    g_q[NTOK * DMODEL];
__device__ float    g_k[NTOK * DMODEL];
__device__ float    g_v[NTOK * DMODEL];
__device__ uint32_t g_attn[NTOK * DMODEL];      // attn out, tf32
__device__ float    g_tmp[NTOK * DMODEL];
__device__ uint32_t g_h[NTOK * FFND];           // FFN mid, tf32
__device__ uint32_t g_wt[50331648];             // all weights, tf32

// weight offsets inside g_wt (grouped by type, all layers contiguous)
#define WQ_OFF 0u
#define WK_OFF 4194304u
#define WV_OFF 8388608u
#define WO_OFF 12582912u
#define W1_OFF 16777216u
#define W2_OFF 33554432u

// ---------------- helpers ----------------
__device__ __forceinline__ uint32_t f2tf(float x) {
    uint32_t r;
    asm("cvt.rna.tf32.f32 %0, %1;" : "=r"(r) : "f"(x));
    return r;
}

__device__ __forceinline__ void mma_tf32(float d[4],
                                         uint32_t a0, uint32_t a1, uint32_t a2, uint32_t a3,
                                         uint32_t b0, uint32_t b1) {
    asm volatile(
        "mma.sync.aligned.m16n8k8.row.col.f32.tf32.tf32.f32 "
        "{%0,%1,%2,%3}, {%4,%5,%6,%7}, {%8,%9}, {%0,%1,%2,%3};\n"
        : "+f"(d[0]), "+f"(d[1]), "+f"(d[2]), "+f"(d[3])
        : "r"(a0), "r"(a1), "r"(a2), "r"(a3), "r"(b0), "r"(b1));
}

__device__ __forceinline__ void cp_async16(uint32_t smem_dst, const void* gsrc) {
    asm volatile("cp.async.ca.shared.global [%0], [%1], 16;\n" :: "r"(smem_dst), "l"(gsrc));
}
__device__ __forceinline__ void cp_commit() { asm volatile("cp.async.commit_group;\n"); }
template<int N>
__device__ __forceinline__ void cp_wait() { asm volatile("cp.async.wait_group %0;\n" :: "n"(N)); }

// ---------------- conversion kernels ----------------
__global__ void conv_tf(const float4* __restrict__ src, uint4* __restrict__ dst, int n4) {
    int i = blockIdx.x * blockDim.x + threadIdx.x;
    if (i < n4) {
        float4 v = src[i];
        dst[i] = make_uint4(f2tf(v.x), f2tf(v.y), f2tf(v.z), f2tf(v.w));
    }
}

__global__ void copy_conv(const float4* __restrict__ src, float4* __restrict__ dst,
                          uint4* __restrict__ dtf, int n4) {
    int i = blockIdx.x * blockDim.x + threadIdx.x;
    if (i < n4) {
        float4 v = src[i];
        dst[i] = v;
        dtf[i] = make_uint4(f2tf(v.x), f2tf(v.y), f2tf(v.z), f2tf(v.w));
    }
}

__global__ void copy_f4(const float4* __restrict__ src, float4* __restrict__ dst, int n4) {
    int i = blockIdx.x * blockDim.x + threadIdx.x;
    if (i < n4) dst[i] = src[i];
}

// ---------------- tf32 tensor-core GEMM with cp.async pipeline ----------------
// C[M,N] = A[M,K] @ W[K,N] + bias (A, W already tf32). Block 128x128, BK=16,
// 256 threads = 8 warps, warp tile 64x32, 4x4 m16n8k8 atoms. 4-stage cp.async.
#define GSTAGES 4
#define ASTRIDE 20
#define BSTRIDE 136
#define A_TILE_WORDS (128 * ASTRIDE)
#define B_TILE_WORDS (16 * BSTRIDE)
#define GEMM_SMEM_BYTES ((GSTAGES * (A_TILE_WORDS + B_TILE_WORDS)) * 4)   // 75776

template<int GELU, int OUTTF>
__launch_bounds__(256, 2)
__global__ void gemm_tc(const uint32_t* __restrict__ A, const uint32_t* __restrict__ W,
                        const float* __restrict__ bias,
                        float* __restrict__ Cf, uint32_t* __restrict__ Ct,
                        int M, int N, int K) {
    extern __shared__ uint32_t sm[];
    const uint32_t sbase = (uint32_t)__cvta_generic_to_shared(sm);

    const int tid  = threadIdx.x;
    const int lane = tid & 31;
    const int wid  = tid >> 5;
    const int wm   = wid & 1;
    const int wn   = wid >> 1;
    const int g    = lane >> 2;
    const int tg   = lane & 3;

    const int row0 = blockIdx.y * 128;
    const int col0 = blockIdx.x * 128;

    const int aRow0 = (tid + 0)   >> 2, aKq0 = (tid + 0)   & 3;
    const int aRow1 = (tid + 256) >> 2, aKq1 = (tid + 256) & 3;
    const int bKr0  = (tid + 0)   >> 5, bNq0 = (tid + 0)   & 31;
    const int bKr1  = (tid + 256) >> 5, bNq1 = (tid + 256) & 31;

    const uint32_t* Ap0 = A + (size_t)(row0 + aRow0) * K + aKq0 * 4;
    const uint32_t* Ap1 = A + (size_t)(row0 + aRow1) * K + aKq1 * 4;
    const uint32_t* Bp0 = W + (size_t)bKr0 * N + col0 + bNq0 * 4;
    const uint32_t* Bp1 = W + (size_t)bKr1 * N + col0 + bNq1 * 4;

    const uint32_t aDst0 = sbase + 4 * (aRow0 * ASTRIDE + aKq0 * 4);
    const uint32_t aDst1 = sbase + 4 * (aRow1 * ASTRIDE + aKq1 * 4);
    const uint32_t bBase = sbase + 4 * (GSTAGES * A_TILE_WORDS);
    const uint32_t bDst0 = bBase + 4 * (bKr0 * BSTRIDE + bNq0 * 4);
    const uint32_t bDst1 = bBase + 4 * (bKr1 * BSTRIDE + bNq1 * 4);

    float acc[4][4][4];
    #pragma unroll
    for (int i = 0; i < 4; ++i)
        #pragma unroll
        for (int j = 0; j < 4; ++j)
            #pragma unroll
            for (int e = 0; e < 4; ++e) acc[i][j][e] = 0.f;

    const int nt = K >> 4;

    #pragma unroll
    for (int s = 0; s < GSTAGES - 1; ++s) {
        cp_async16(aDst0 + 4 * s * A_TILE_WORDS, Ap0 + (size_t)s * 16);
        cp_async16(aDst1 + 4 * s * A_TILE_WORDS, Ap1 + (size_t)s * 16);
        cp_async16(bDst0 + 4 * s * B_TILE_WORDS, Bp0 + (size_t)s * 16 * N);
        cp_async16(bDst1 + 4 * s * B_TILE_WORDS, Bp1 + (size_t)s * 16 * N);
        cp_commit();
    }

    for (int t = 0; t < nt; ++t) {
        cp_wait<GSTAGES - 2>();
        __syncthreads();

        const int stg = t & (GSTAGES - 1);
        const uint32_t* As = sm + stg * A_TILE_WORDS;
        const uint32_t* Bs = sm + GSTAGES * A_TILE_WORDS + stg * B_TILE_WORDS;

        #pragma unroll
        for (int ks = 0; ks < 2; ++ks) {
            const int k0 = ks * 8;
            uint32_t af[4][4], bf[4][2];
            #pragma unroll
            for (int mt = 0; mt < 4; ++mt) {
                const int r = wm * 64 + mt * 16 + g;
                af[mt][0] = As[r * ASTRIDE + k0 + tg];
                af[mt][1] = As[(r + 8) * ASTRIDE + k0 + tg];
                af[mt][2] = As[r * ASTRIDE + k0 + tg + 4];
                af[mt][3] = As[(r + 8) * ASTRIDE + k0 + tg + 4];
            }
            #pragma unroll
            for (int ntc = 0; ntc < 4; ++ntc) {
                const int c = wn * 32 + ntc * 8 + g;
                bf[ntc][0] = Bs[(k0 + tg) * BSTRIDE + c];
                bf[ntc][1] = Bs[(k0 + tg + 4) * BSTRIDE + c];
            }
            #pragma unroll
            for (int mt = 0; mt < 4; ++mt)
                #pragma unroll
                for (int ntc = 0; ntc < 4; ++ntc)
                    mma_tf32(acc[mt][ntc], af[mt][0], af[mt][1], af[mt][2], af[mt][3],
                             bf[ntc][0], bf[ntc][1]);
        }

        if (t + GSTAGES - 1 < nt) {
            const int tn = t + GSTAGES - 1;
            const int sn = tn & (GSTAGES - 1);
            cp_async16(aDst0 + 4 * sn * A_TILE_WORDS, Ap0 + (size_t)tn * 16);
            cp_async16(aDst1 + 4 * sn * A_TILE_WORDS, Ap1 + (size_t)tn * 16);
            cp_async16(bDst0 + 4 * sn * B_TILE_WORDS, Bp0 + (size_t)tn * 16 * N);
            cp_async16(bDst1 + 4 * sn * B_TILE_WORDS, Bp1 + (size_t)tn * 16 * N);
        }
        cp_commit();
    }

    #pragma unroll
    for (int ntc = 0; ntc < 4; ++ntc) {
        const int col = col0 + wn * 32 + ntc * 8 + 2 * tg;
        const float2 bb = *(const float2*)(bias + col);
        #pragma unroll
        for (int mt = 0; mt < 4; ++mt) {
            const int row = row0 + wm * 64 + mt * 16 + g;
            float2 lo, hi;
            lo.x = acc[mt][ntc][0] + bb.x;
            lo.y = acc[mt][ntc][1] + bb.y;
            hi.x = acc[mt][ntc][2] + bb.x;
            hi.y = acc[mt][ntc][3] + bb.y;
            if (GELU) {
                lo.x *= normcdff(lo.x); lo.y *= normcdff(lo.y);
                hi.x *= normcdff(hi.x); hi.y *= normcdff(hi.y);
            }
            if (OUTTF) {
                uint2 ulo = make_uint2(f2tf(lo.x), f2tf(lo.y));
                uint2 uhi = make_uint2(f2tf(hi.x), f2tf(hi.y));
                *(uint2*)(Ct + (size_t)row * N + col)       = ulo;
                *(uint2*)(Ct + (size_t)(row + 8) * N + col) = uhi;
            } else {
                *(float2*)(Cf + (size_t)row * N + col)       = lo;
                *(float2*)(Cf + (size_t)(row + 8) * N + col) = hi;
            }
        }
    }
}

// ---------------- tensor-core paged-KV flash attention ----------------
// grid (SQ/128, NH, NB), 256 threads = 8 warps, each warp a 16-row Q strip.
// Q fragments in regs; K,V double-buffered tf32 smem tiles (64 kv x 64 d);
// P warp-private smem strip. One __syncthreads per kv tile.
#define AT_KVW (64 * 72)                 // words per K or V buffer
#define AT_PSW (16 * 68)                 // words per warp P strip
#define ATTN_SMEM_BYTES ((4 * AT_KVW + 8 * AT_PSW) * 4)   // 108544

__launch_bounds__(256, 1)
__global__ void attn_tc(const float* __restrict__ q, const float* __restrict__ knew,
                        const float* __restrict__ vnew, const float* __restrict__ ptab,
                        const int* __restrict__ kvidx, uint32_t* __restrict__ out) {
    extern __shared__ uint32_t sm[];
    uint32_t* KtB = sm;                         // [2][64][72], swizzled [d][j]
    uint32_t* VtB = sm + 2 * AT_KVW;            // [2][64][72], [j][d]
    const int tid  = threadIdx.x;
    const int lane = tid & 31;
    const int wid  = tid >> 5;
    const int g    = lane >> 2;
    const int tg   = lane & 3;
    uint32_t* Ps = sm + 4 * AT_KVW + wid * AT_PSW;   // [16][68]

    const int qt = blockIdx.x, h = blockIdx.y, b = blockIdx.z;
    const int row0 = qt * 128 + wid * 16;
    const float scale = 0.125f;

    // persistent Q fragments
    uint32_t qf[8][4];
    {
        const float* q0 = q + (size_t)(b * SQ + row0 + g) * DMODEL + h * DH;
        const float* q1 = q0 + 8 * DMODEL;
        #pragma unroll
        for (int s = 0; s < 8; ++s) {
            qf[s][0] = f2tf(q0[8 * s + tg] * scale);
            qf[s][1] = f2tf(q1[8 * s + tg] * scale);
            qf[s][2] = f2tf(q0[8 * s + tg + 4] * scale);
            qf[s][3] = f2tf(q1[8 * s + tg + 4] * scale);
        }
    }

    float o[8][4];
    #pragma unroll
    for (int da = 0; da < 8; ++da)
        #pragma unroll
        for (int e = 0; e < 4; ++e) o[da][e] = 0.f;
    float m0 = -1e30f, m1 = -1e30f, l0 = 0.f, l1 = 0.f;

    float4 kst[4], vst[4];
    auto ldtile = [&](int kt) {
        #pragma unroll
        for (int r = 0; r < 4; ++r) {
            int c = tid + r * 256;
            int tok = c >> 4;
            int d4  = (c & 15) << 2;
            int kv = kt * 64 + tok;
            const float *kp, *vp;
            if (kv < CACHED_TOK) {
                int page = kvidx[b * PPS + (kv >> 4)];
                size_t base = (size_t)page * (2 * PAGE * NH * DH)
                            + (size_t)(kv & 15) * (NH * DH) + h * DH + d4;
                kp = ptab + base;
                vp = ptab + base + PAGE * NH * DH;
            } else {
                size_t off = (size_t)(b * SQ + (kv - CACHED_TOK)) * DMODEL + h * DH + d4;
                kp = knew + off;
                vp = vnew + off;
            }
            kst[r] = *(const float4*)kp;
            vst[r] = *(const float4*)vp;
        }
    };
    auto sttile = [&](int buf) {
        uint32_t* Kb = KtB + buf * AT_KVW;
        uint32_t* Vb = VtB + buf * AT_KVW;
        #pragma unroll
        for (int r = 0; r < 4; ++r) {
            int c = tid + r * 256;
            int tok = c >> 4;
            int d4  = (c & 15) << 2;
            int colp = tok ^ d4;                      // swizzle: col = j ^ (d & 60)
            Kb[(d4 + 0) * 72 + colp] = f2tf(kst[r].x);
            Kb[(d4 + 1) * 72 + colp] = f2tf(kst[r].y);
            Kb[(d4 + 2) * 72 + colp] = f2tf(kst[r].z);
            Kb[(d4 + 3) * 72 + colp] = f2tf(kst[r].w);
            *(uint4*)&Vb[tok * 72 + d4] =
                make_uint4(f2tf(vst[r].x), f2tf(vst[r].y), f2tf(vst[r].z), f2tf(vst[r].w));
        }
    };

    ldtile(0);
    sttile(0);
    __syncthreads();

    int buf = 0;
    for (int kt = 0; kt < KVLEN / 64; ++kt) {
        if (kt + 1 < KVLEN / 64) ldtile(kt + 1);

        // ---- S = Q K^T (16 x 64 strip) ----
        const uint32_t* Kb = KtB + buf * AT_KVW;
        float sc[8][4];
        #pragma unroll
        for (int a = 0; a < 8; ++a)
            #pragma unroll
            for (int e = 0; e < 4; ++e) sc[a][e] = 0.f;
        #pragma unroll
        for (int s = 0; s < 8; ++s) {
            const uint32_t a0 = qf[s][0], a1 = qf[s][1], a2 = qf[s][2], a3 = qf[s][3];
            const int rk0 = (8 * s + tg) * 72;
            const int rk1 = (8 * s + tg + 4) * 72;
            #pragma unroll
            for (int a = 0; a < 8; ++a) {
                uint32_t b0 = Kb[rk0 + (8 * (a ^ s) + g)];
                uint32_t b1 = Kb[rk1 + (8 * (a ^ s) + (g ^ 4))];
                mma_tf32(sc[a], a0, a1, a2, a3, b0, b1);
            }
        }

        // ---- online softmax ----
        float mx0 = -1e30f, mx1 = -1e30f;
        #pragma unroll
        for (int a = 0; a < 8; ++a) {
            mx0 = fmaxf(mx0, fmaxf(sc[a][0], sc[a][1]));
            mx1 = fmaxf(mx1, fmaxf(sc[a][2], sc[a][3]));
        }
        mx0 = fmaxf(mx0, __shfl_xor_sync(0xffffffffu, mx0, 1));
        mx0 = fmaxf(mx0, __shfl_xor_sync(0xffffffffu, mx0, 2));
        mx1 = fmaxf(mx1, __shfl_xor_sync(0xffffffffu, mx1, 1));
        mx1 = fmaxf(mx1, __shfl_xor_sync(0xffffffffu, mx1, 2));
        const float mn0 = fmaxf(m0, mx0), mn1 = fmaxf(m1, mx1);
        const float c0 = __expf(m0 - mn0), c1 = __expf(m1 - mn1);
        float s0 = 0.f, s1 = 0.f;
        #pragma unroll
        for (int a = 0; a < 8; ++a) {
            sc[a][0] = __expf(sc[a][0] - mn0); s0 += sc[a][0];
            sc[a][1] = __expf(sc[a][1] - mn0); s0 += sc[a][1];
            sc[a][2] = __expf(sc[a][2] - mn1); s1 += sc[a][2];
            sc[a][3] = __expf(sc[a][3] - mn1); s1 += sc[a][3];
        }
        s0 += __shfl_xor_sync(0xffffffffu, s0, 1);
        s0 += __shfl_xor_sync(0xffffffffu, s0, 2);
        s1 += __shfl_xor_sync(0xffffffffu, s1, 1);
        s1 += __shfl_xor_sync(0xffffffffu, s1, 2);
        l0 = l0 * c0 + s0;  l1 = l1 * c1 + s1;
        m0 = mn0;  m1 = mn1;
        #pragma unroll
        for (int da = 0; da < 8; ++da) {
            o[da][0] *= c0; o[da][1] *= c0;
            o[da][2] *= c1; o[da][3] *= c1;
        }

        // ---- P -> warp-local smem (tf32) ----
        #pragma unroll
        for (int a = 0; a < 8; ++a) {
            const int cb = 8 * a + 2 * tg;
            Ps[g * 68 + cb]           = f2tf(sc[a][0]);
            Ps[g * 68 + cb + 1]       = f2tf(sc[a][1]);
            Ps[(g + 8) * 68 + cb]     = f2tf(sc[a][2]);
            Ps[(g + 8) * 68 + cb + 1] = f2tf(sc[a][3]);
        }
        __syncwarp();

        // ---- O += P V ----
        const uint32_t* Vb = VtB + buf * AT_KVW;
        #pragma unroll
        for (int s = 0; s < 8; ++s) {
            uint32_t a0 = Ps[g * 68 + 8 * s + tg];
            uint32_t a1 = Ps[(g + 8) * 68 + 8 * s + tg];
            uint32_t a2 = Ps[g * 68 + 8 * s + tg + 4];
            uint32_t a3 = Ps[(g + 8) * 68 + 8 * s + tg + 4];
            const int rk0 = (8 * s + tg) * 72;
            const int rk1 = (8 * s + tg + 4) * 72;
            #pragma unroll
            for (int da = 0; da < 8; ++da) {
                uint32_t b0 = Vb[rk0 + 8 * da + g];
                uint32_t b1 = Vb[rk1 + 8 * da + g];
                mma_tf32(o[da], a0, a1, a2, a3, b0, b1);
            }
        }

        if (kt + 1 < KVLEN / 64) {
            sttile(buf ^ 1);
            __syncthreads();
            buf ^= 1;
        }
    }

    // ---- normalize and store tf32 output ----
    const float inv0 = 1.f / l0, inv1 = 1.f / l1;
    uint32_t* o0 = out + (size_t)(b * SQ + row0 + g) * DMODEL + h * DH;
    uint32_t* o1 = o0 + 8 * DMODEL;
    #pragma unroll
    for (int da = 0; da < 8; ++da) {
        const int col = 8 * da + 2 * tg;
        *(uint2*)&o0[col] = make_uint2(f2tf(o[da][0] * inv0), f2tf(o[da][1] * inv0));
        *(uint2*)&o1[col] = make_uint2(f2tf(o[da][2] * inv1), f2tf(o[da][3] * inv1));
    }
}

// ---------------- fused residual-add + LayerNorm (fp32 + tf32 outputs) ----------------
__launch_bounds__(256)
__global__ void ln_kernel(const float* __restrict__ resid, const float* __restrict__ y,
                          const float* __restrict__ gg, const float* __restrict__ bb,
                          float* __restrict__ outf, uint32_t* __restrict__ outt) {
    const int row = blockIdx.x, tid = threadIdx.x;
    __shared__ float redS[8], redS2[8];
    float4 rv = *(const float4*)(resid + (size_t)row * DMODEL + tid * 4);
    float4 yv = *(const float4*)(y     + (size_t)row * DMODEL + tid * 4);
    float v0 = rv.x + yv.x, v1 = rv.y + yv.y, v2 = rv.z + yv.z, v3 = rv.w + yv.w;
    float s  = v0 + v1 + v2 + v3;
    float s2 = v0 * v0 + v1 * v1 + v2 * v2 + v3 * v3;
    #pragma unroll
    for (int o = 16; o > 0; o >>= 1) {
        s  += __shfl_xor_sync(0xffffffffu, s,  o);
        s2 += __shfl_xor_sync(0xffffffffu, s2, o);
    }
    if ((tid & 31) == 0) { redS[tid >> 5] = s; redS2[tid >> 5] = s2; }
    __syncthreads();
    if (tid < 32) {
        float a  = (tid < 8) ? redS[tid]  : 0.f;
        float a2 = (tid < 8) ? redS2[tid] : 0.f;
        #pragma unroll
        for (int o = 4; o > 0; o >>= 1) {
            a  += __shfl_xor_sync(0xffffffffu, a,  o);
            a2 += __shfl_xor_sync(0xffffffffu, a2, o);
        }
        if (tid == 0) { redS[0] = a; redS2[0] = a2; }
    }
    __syncthreads();
    const float mean = redS[0] * (1.f / DMODEL);
    const float var  = redS2[0] * (1.f / DMODEL) - mean * mean;
    const float inv  = rsqrtf(var + 1e-5f);
    float4 gv = *(const float4*)(gg + tid * 4);
    float4 bv = *(const float4*)(bb + tid * 4);
    float4 o;
    o.x = (v0 - mean) * inv * gv.x + bv.x;
    o.y = (v1 - mean) * inv * gv.y + bv.y;
    o.z = (v2 - mean) * inv * gv.z + bv.z;
    o.w = (v3 - mean) * inv * gv.w + bv.w;
    *(float4*)(outf + (size_t)row * DMODEL + tid * 4) = o;
    *(uint4*)(outt + (size_t)row * DMODEL + tid * 4) =
        make_uint4(f2tf(o.x), f2tf(o.y), f2tf(o.z), f2tf(o.w));
}

// ---------------- launcher ----------------
extern "C" void kernel_launch(void* const* d_in, const int* in_sizes, int n_in,
                              void* d_out, int out_size) {
    const float* x      = (const float*)d_in[0];
    const int*   kvidx  = (const int*)d_in[3];
    const float* ptab   = (const float*)d_in[5];
    const float* Wq = (const float*)d_in[6];
    const float* bq = (const float*)d_in[7];
    const float* Wk = (const float*)d_in[8];
    const float* bk = (const float*)d_in[9];
    const float* Wv = (const float*)d_in[10];
    const float* bv = (const float*)d_in[11];
    const float* Wo = (const float*)d_in[12];
    const float* bo = (const float*)d_in[13];
    const float* ln1g = (const float*)d_in[14];
    const float* ln1b = (const float*)d_in[15];
    const float* W1 = (const float*)d_in[16];
    const float* b1 = (const float*)d_in[17];
    const float* W2 = (const float*)d_in[18];
    const float* b2 = (const float*)d_in[19];
    const float* ln2g = (const float*)d_in[20];
    const float* ln2b = (const float*)d_in[21];

    float *gx, *gq, *gk, *gv, *gt;
    uint32_t *gxt, *ga, *gh, *gwt;
    cudaGetSymbolAddress((void**)&gx,  g_x);
    cudaGetSymbolAddress((void**)&gxt, g_xt);
    cudaGetSymbolAddress((void**)&gq,  g_q);
    cudaGetSymbolAddress((void**)&gk,  g_k);
    cudaGetSymbolAddress((void**)&gv,  g_v);
    cudaGetSymbolAddress((void**)&ga,  g_attn);
    cudaGetSymbolAddress((void**)&gt,  g_tmp);
    cudaGetSymbolAddress((void**)&gh,  g_h);
    cudaGetSymbolAddress((void**)&gwt, g_wt);

    cudaFuncSetAttribute((const void*)attn_tc,
                         cudaFuncAttributeMaxDynamicSharedMemorySize, ATTN_SMEM_BYTES);
    cudaFuncSetAttribute((const void*)gemm_tc<0, 0>,
                         cudaFuncAttributeMaxDynamicSharedMemorySize, GEMM_SMEM_BYTES);
    cudaFuncSetAttribute((const void*)gemm_tc<1, 1>,
                         cudaFuncAttributeMaxDynamicSharedMemorySize, GEMM_SMEM_BYTES);

    // ---- weight conversion (all layers, once per call) ----
    {
        const int nproj4 = TL * DMODEL * DMODEL / 4;      // 1,048,576
        const int nffn4  = TL * DMODEL * FFND / 4;        // 4,194,304
        conv_tf<<<(nproj4 + 255) / 256, 256>>>((const float4*)Wq, (uint4*)(gwt + WQ_OFF), nproj4);
        conv_tf<<<(nproj4 + 255) / 256, 256>>>((const float4*)Wk, (uint4*)(gwt + WK_OFF), nproj4);
        conv_tf<<<(nproj4 + 255) / 256, 256>>>((const float4*)Wv, (uint4*)(gwt + WV_OFF), nproj4);
        conv_tf<<<(nproj4 + 255) / 256, 256>>>((const float4*)Wo, (uint4*)(gwt + WO_OFF), nproj4);
        conv_tf<<<(nffn4 + 255) / 256, 256>>>((const float4*)W1, (uint4*)(gwt + W1_OFF), nffn4);
        conv_tf<<<(nffn4 + 255) / 256, 256>>>((const float4*)W2, (uint4*)(gwt + W2_OFF), nffn4);
    }

    const int n4 = NTOK * DMODEL / 4;
    copy_conv<<<(n4 + 255) / 256, 256>>>((const float4*)x, (float4*)gx, (uint4*)gxt, n4);

    dim3 gProj(DMODEL / 128, NTOK / 128);
    dim3 gF1(FFND / 128, NTOK / 128);
    dim3 gAttn(SQ / 128, NH, NB);

    for (int l = 0; l < TL; ++l) {
        const uint32_t* Wq_l = gwt + WQ_OFF + (size_t)l * DMODEL * DMODEL;
        const uint32_t* Wk_l = gwt + WK_OFF + (size_t)l * DMODEL * DMODEL;
        const uint32_t* Wv_l = gwt + WV_OFF + (size_t)l * DMODEL * DMODEL;
        const uint32_t* Wo_l = gwt + WO_OFF + (size_t)l * DMODEL * DMODEL;
        const uint32_t* W1_l = gwt + W1_OFF + (size_t)l * DMODEL * FFND;
        const uint32_t* W2_l = gwt + W2_OFF + (size_t)l * FFND * DMODEL;
        const float* ptab_l = ptab + (size_t)l * NUM_PAGES * 2 * PAGE * NH * DH;

        gemm_tc<0, 0><<<gProj, 256, GEMM_SMEM_BYTES>>>(gxt, Wq_l, bq + l * DMODEL, gq, nullptr, NTOK, DMODEL, DMODEL);
        gemm_tc<0, 0><<<gProj, 256, GEMM_SMEM_BYTES>>>(gxt, Wk_l, bk + l * DMODEL, gk, nullptr, NTOK, DMODEL, DMODEL);
        gemm_tc<0, 0><<<gProj, 256, GEMM_SMEM_BYTES>>>(gxt, Wv_l, bv + l * DMODEL, gv, nullptr, NTOK, DMODEL, DMODEL);

        attn_tc<<<gAttn, 256, ATTN_SMEM_BYTES>>>(gq, gk, gv, ptab_l, kvidx, ga);

        gemm_tc<0, 0><<<gProj, 256, GEMM_SMEM_BYTES>>>(ga, Wo_l, bo + l * DMODEL, gt, nullptr, NTOK, DMODEL, DMODEL);
        ln_kernel<<<NTOK, 256>>>(gx, gt, ln1g + l * DMODEL, ln1b + l * DMODEL, gx, gxt);

        gemm_tc<1, 1><<<gF1, 256, GEMM_SMEM_BYTES>>>(gxt, W1_l, b1 + l * FFND, nullptr, gh, NTOK, FFND, DMODEL);
        gemm_tc<0, 0><<<gProj, 256, GEMM_SMEM_BYTES>>>(gh, W2_l, b2 + l * DMODEL, gt, nullptr, NTOK, DMODEL, FFND);
        ln_kernel<<<NTOK, 256>>>(gx, gt, ln2g + l * DMODEL, ln2b + l * DMODEL, gx, gxt);
    }

    copy_f4<<<(n4 + 255) / 256, 256>>>((const float4*)gx, (float4*)d_out, n4);
}